// round 1
// baseline (speedup 1.0000x reference)
#include <cuda_runtime.h>
#include <cstdint>

// Problem constants
#define DIMM  1024
#define HEADS 16
#define HDIM  64
#define BATCH 16
#define SEQ   512
// rows of the projection GEMMs
#define MROWS (BATCH*SEQ)  // 8192

// ---------------- scratch (device globals; no cudaMalloc allowed) ----------
__device__ float g_Q[(size_t)BATCH*HEADS*SEQ*HDIM];   // [b,h,s,d]  32 MB
__device__ float g_K[(size_t)BATCH*HEADS*SEQ*HDIM];   // 32 MB
__device__ float g_V[(size_t)BATCH*HEADS*SEQ*HDIM];   // 32 MB
__device__ float g_S[(size_t)BATCH*HEADS*SEQ*SEQ];    // [bh,sq,sk] 256 MB
__device__ float g_O[(size_t)BATCH*SEQ*DIMM];         // [b,s,h*d]  32 MB

// ---------------- helpers ---------------------------------------------------
__device__ __forceinline__ float to_tf32(float x) {
    uint32_t u;
    asm("cvt.rna.tf32.f32 %0, %1;" : "=r"(u) : "f"(x));
    return __uint_as_float(u);
}

__device__ __forceinline__ void mma8(float* c,
                                     uint32_t a0, uint32_t a1, uint32_t a2, uint32_t a3,
                                     uint32_t b0, uint32_t b1) {
    asm volatile(
        "mma.sync.aligned.m16n8k8.row.col.f32.tf32.tf32.f32 "
        "{%0,%1,%2,%3},{%4,%5,%6,%7},{%8,%9},{%0,%1,%2,%3};"
        : "+f"(c[0]), "+f"(c[1]), "+f"(c[2]), "+f"(c[3])
        : "r"(a0), "r"(a1), "r"(a2), "r"(a3), "r"(b0), "r"(b1));
}

// RoPE: tables are TILED (cos[s,j] = cos(t * freqs[j mod 32])) but rotation
// pairs ADJACENT elements (2i, 2i+1) -- exactly as the reference does.
// freqs[m] = 10000^(-m/32) = exp2(-m * log2(10000)/32)
__device__ __forceinline__ void rope_pair(float& e, float& o, int t, int d /*even*/) {
    const float LOG2_10000_OVER_32 = 0.41524101186092028f;
    int   i0  = d & 31;                       // even, 0..30
    float fr0 = exp2f(-(float)i0       * LOG2_10000_OVER_32);
    float fr1 = exp2f(-(float)(i0 + 1) * LOG2_10000_OVER_32);
    float tf  = (float)t;
    float s0, c0, s1, c1;
    sincosf(tf * fr0, &s0, &c0);
    sincosf(tf * fr1, &s1, &c1);
    float ne = e * c0 - o * s0;   // out[2i]   = x[2i]*cos(f(2i))   - x[2i+1]*sin(f(2i))
    float no = o * c1 + e * s1;   // out[2i+1] = x[2i+1]*cos(f(2i+1)) + x[2i]*sin(f(2i+1))
    e = ne; o = no;
}

// ---------------- the GEMM kernel (tf32 mma, 64x64x16 tiles, 4 warps) -------
// MODE: 0 = Q proj (+RoPE, out g_Q [b,h,s,d])
//       1 = K proj (+RoPE, out g_K)
//       2 = V proj (out g_V)
//       3 = scores  S = Q K^T * scale      (batched over z = b*H+h, B transposed)
//       4 = PV      O = P V                (batched over z)
//       5 = output  out = O @ Wo + bo
template <int MODE>
__global__ void __launch_bounds__(128) gemm_k(const float* __restrict__ Ain,
                                              const float* __restrict__ Bin,
                                              float*       __restrict__ Cout,
                                              const float* __restrict__ bias) {
    constexpr int  KDIM = (MODE <= 2 || MODE == 5) ? 1024 : (MODE == 3 ? 64 : 512);
    constexpr int  LDA  = (MODE <= 2 || MODE == 5) ? 1024 : (MODE == 3 ? 64 : 512);
    constexpr int  LDB  = (MODE <= 2 || MODE == 5) ? 1024 : 64;
    constexpr bool TB   = (MODE == 3);   // B stored [N,K] row-major (K matrix)

    const int tid  = threadIdx.x;
    const int lane = tid & 31;
    const int warp = tid >> 5;
    const int wm   = warp >> 1;          // 2x2 warp grid, each warp 32x32
    const int wn   = warp & 1;
    const int mBase = blockIdx.y * 64;
    const int nBase = blockIdx.x * 64;
    const int z     = blockIdx.z;

    const float* A;
    const float* Bp;
    if constexpr (MODE <= 2)      { A = Ain;                              Bp = Bin; }
    else if constexpr (MODE == 3) { A = g_Q + (size_t)z * SEQ * HDIM;     Bp = g_K + (size_t)z * SEQ * HDIM; }
    else if constexpr (MODE == 4) { A = g_S + (size_t)z * SEQ * SEQ;      Bp = g_V + (size_t)z * SEQ * HDIM; }
    else                          { A = g_O;                              Bp = Bin; }

    __shared__ float As[64 * 20];                       // stride 20: conflict-free frag reads
    __shared__ float Bs[TB ? (64 * 20) : (16 * 72)];    // NN: stride 72 (== 8 mod 32)

    float acc[2][4][4];
    #pragma unroll
    for (int i = 0; i < 2; i++)
        #pragma unroll
        for (int j = 0; j < 4; j++)
            #pragma unroll
            for (int k = 0; k < 4; k++) acc[i][j][k] = 0.f;

    for (int k0 = 0; k0 < KDIM; k0 += 16) {
        // --- load A tile 64x16 (convert to tf32) ---
        #pragma unroll
        for (int i = 0; i < 2; i++) {
            int idx = tid + i * 128;
            int r = idx >> 2, c4 = (idx & 3) * 4;
            float4 v = *reinterpret_cast<const float4*>(A + (size_t)(mBase + r) * LDA + k0 + c4);
            float* d = &As[r * 20 + c4];
            d[0] = to_tf32(v.x); d[1] = to_tf32(v.y); d[2] = to_tf32(v.z); d[3] = to_tf32(v.w);
        }
        // --- load B tile ---
        if constexpr (TB) {      // B = K matrix [N rows, K cols], load like A
            #pragma unroll
            for (int i = 0; i < 2; i++) {
                int idx = tid + i * 128;
                int r = idx >> 2, c4 = (idx & 3) * 4;
                float4 v = *reinterpret_cast<const float4*>(Bp + (size_t)(nBase + r) * LDB + k0 + c4);
                float* d = &Bs[r * 20 + c4];
                d[0] = to_tf32(v.x); d[1] = to_tf32(v.y); d[2] = to_tf32(v.z); d[3] = to_tf32(v.w);
            }
        } else {                 // B row-major [K, N]: tile 16x64
            #pragma unroll
            for (int i = 0; i < 2; i++) {
                int idx = tid + i * 128;
                int r = idx >> 4, c4 = (idx & 15) * 4;
                float4 v = *reinterpret_cast<const float4*>(Bp + (size_t)(k0 + r) * LDB + nBase + c4);
                float* d = &Bs[r * 72 + c4];
                d[0] = to_tf32(v.x); d[1] = to_tf32(v.y); d[2] = to_tf32(v.z); d[3] = to_tf32(v.w);
            }
        }
        __syncthreads();

        #pragma unroll
        for (int kk = 0; kk < 16; kk += 8) {
            const int cc = kk + (lane & 3);
            uint32_t af[2][4];
            #pragma unroll
            for (int mt = 0; mt < 2; mt++) {
                int r0 = (wm * 32 + mt * 16 + (lane >> 2)) * 20;
                af[mt][0] = __float_as_uint(As[r0 + cc]);
                af[mt][1] = __float_as_uint(As[r0 + 160 + cc]);      // +8 rows
                af[mt][2] = __float_as_uint(As[r0 + cc + 4]);
                af[mt][3] = __float_as_uint(As[r0 + 160 + cc + 4]);
            }
            uint32_t bf[4][2];
            #pragma unroll
            for (int nt = 0; nt < 4; nt++) {
                int nb = wn * 32 + nt * 8 + (lane >> 2);
                if constexpr (TB) {
                    bf[nt][0] = __float_as_uint(Bs[nb * 20 + kk + (lane & 3)]);
                    bf[nt][1] = __float_as_uint(Bs[nb * 20 + kk + (lane & 3) + 4]);
                } else {
                    bf[nt][0] = __float_as_uint(Bs[(kk + (lane & 3)) * 72 + nb]);
                    bf[nt][1] = __float_as_uint(Bs[(kk + (lane & 3) + 4) * 72 + nb]);
                }
            }
            #pragma unroll
            for (int mt = 0; mt < 2; mt++)
                #pragma unroll
                for (int nt = 0; nt < 4; nt++)
                    mma8(acc[mt][nt], af[mt][0], af[mt][1], af[mt][2], af[mt][3],
                         bf[nt][0], bf[nt][1]);
        }
        __syncthreads();
    }

    // --- epilogue ---
    #pragma unroll
    for (int mt = 0; mt < 2; mt++) {
        #pragma unroll
        for (int nt = 0; nt < 4; nt++) {
            int row = mBase + wm * 32 + mt * 16 + (lane >> 2);
            int col = nBase + wn * 32 + nt * 8 + 2 * (lane & 3);   // even -> rope pair
            #pragma unroll
            for (int half = 0; half < 2; half++) {
                int   rr = row + half * 8;
                float e  = acc[mt][nt][half * 2 + 0];
                float o  = acc[mt][nt][half * 2 + 1];
                if constexpr (MODE <= 1) rope_pair(e, o, rr & (SEQ - 1), col & (HDIM - 1));
                if constexpr (MODE <= 2) {
                    int b = rr >> 9, s = rr & (SEQ - 1);
                    int h = col >> 6, d = col & (HDIM - 1);
                    float* out = (MODE == 0) ? g_Q : ((MODE == 1) ? g_K : g_V);
                    size_t off = (((size_t)(b * HEADS + h)) * SEQ + s) * HDIM + d;
                    *reinterpret_cast<float2*>(out + off) = make_float2(e, o);
                } else if constexpr (MODE == 3) {
                    size_t off = (size_t)z * SEQ * SEQ + (size_t)rr * SEQ + col;
                    *reinterpret_cast<float2*>(g_S + off) = make_float2(e * 0.125f, o * 0.125f);
                } else if constexpr (MODE == 4) {
                    int b = z >> 4, h = z & 15;
                    size_t off = ((size_t)(b * SEQ + rr)) * DIMM + h * HDIM + col;
                    *reinterpret_cast<float2*>(g_O + off) = make_float2(e, o);
                } else {
                    size_t off = (size_t)rr * DIMM + col;
                    *reinterpret_cast<float2*>(Cout + off) =
                        make_float2(e + bias[col], o + bias[col + 1]);
                }
            }
        }
    }
}

// ---------------- row softmax over g_S (one warp per 512-row) ---------------
__global__ void __launch_bounds__(128) softmax_k() {
    int row  = blockIdx.x * 4 + (threadIdx.x >> 5);
    int lane = threadIdx.x & 31;
    float4* p = reinterpret_cast<float4*>(g_S + (size_t)row * SEQ);
    float4 v[4];
    float mx = -1e30f;
    #pragma unroll
    for (int i = 0; i < 4; i++) {
        v[i] = p[lane + i * 32];
        mx = fmaxf(mx, fmaxf(fmaxf(v[i].x, v[i].y), fmaxf(v[i].z, v[i].w)));
    }
    #pragma unroll
    for (int off = 16; off; off >>= 1) mx = fmaxf(mx, __shfl_xor_sync(0xffffffffu, mx, off));
    float sum = 0.f;
    #pragma unroll
    for (int i = 0; i < 4; i++) {
        v[i].x = __expf(v[i].x - mx); v[i].y = __expf(v[i].y - mx);
        v[i].z = __expf(v[i].z - mx); v[i].w = __expf(v[i].w - mx);
        sum += v[i].x + v[i].y + v[i].z + v[i].w;
    }
    #pragma unroll
    for (int off = 16; off; off >>= 1) sum += __shfl_xor_sync(0xffffffffu, sum, off);
    float inv = 1.0f / sum;
    #pragma unroll
    for (int i = 0; i < 4; i++) {
        v[i].x *= inv; v[i].y *= inv; v[i].z *= inv; v[i].w *= inv;
        p[lane + i * 32] = v[i];
    }
}

// ---------------- launch -----------------------------------------------------
extern "C" void kernel_launch(void* const* d_in, const int* in_sizes, int n_in,
                              void* d_out, int out_size) {
    (void)in_sizes; (void)n_in; (void)out_size;
    const float* x   = (const float*)d_in[0];
    const float* ctx = (const float*)d_in[1];
    const float* Wq  = (const float*)d_in[2];
    const float* Wk  = (const float*)d_in[3];
    const float* Wv  = (const float*)d_in[4];
    const float* Wo  = (const float*)d_in[5];
    const float* bo  = (const float*)d_in[6];
    float* out = (float*)d_out;

    dim3 blk(128);
    // projections (+fused RoPE for Q,K), output in [b,h,s,d] layout
    gemm_k<0><<<dim3(16, 128, 1), blk>>>(x,   Wq, nullptr, nullptr);
    gemm_k<1><<<dim3(16, 128, 1), blk>>>(ctx, Wk, nullptr, nullptr);
    gemm_k<2><<<dim3(16, 128, 1), blk>>>(ctx, Wv, nullptr, nullptr);
    // scores = Q K^T * scale (batched over 256 (b,h) pairs)
    gemm_k<3><<<dim3(8, 8, 256), blk>>>(nullptr, nullptr, nullptr, nullptr);
    // softmax rows (256*512 rows of 512)
    softmax_k<<<(BATCH * HEADS * SEQ) / 4, blk>>>();
    // O = P V
    gemm_k<4><<<dim3(1, 8, 256), blk>>>(nullptr, nullptr, nullptr, nullptr);
    // out = O @ Wo + bo
    gemm_k<5><<<dim3(16, 128, 1), blk>>>(nullptr, Wo, out, bo);
}

// round 3
// speedup vs baseline: 1.1394x; 1.1394x over previous
#include <cuda_runtime.h>
#include <cstdint>

// Problem constants
#define DIMM  1024
#define HEADS 16
#define HDIM  64
#define BATCH 16
#define SEQ   512

// ---------------- scratch (device globals; no cudaMalloc allowed) ----------
__device__ float g_Q[(size_t)BATCH*HEADS*SEQ*HDIM];   // [b,h,s,d]  32 MB
__device__ float g_K[(size_t)BATCH*HEADS*SEQ*HDIM];   // 32 MB
__device__ float g_V[(size_t)BATCH*HEADS*SEQ*HDIM];   // 32 MB
__device__ float g_O[(size_t)BATCH*SEQ*DIMM];         // [b,s,h*d]  32 MB

// ---------------- helpers ---------------------------------------------------
__device__ __forceinline__ float to_tf32(float x) {
    uint32_t u;
    asm("cvt.rna.tf32.f32 %0, %1;" : "=r"(u) : "f"(x));
    return __uint_as_float(u);
}

__device__ __forceinline__ void mma8(float* c,
                                     uint32_t a0, uint32_t a1, uint32_t a2, uint32_t a3,
                                     uint32_t b0, uint32_t b1) {
    asm volatile(
        "mma.sync.aligned.m16n8k8.row.col.f32.tf32.tf32.f32 "
        "{%0,%1,%2,%3},{%4,%5,%6,%7},{%8,%9},{%0,%1,%2,%3};"
        : "+f"(c[0]), "+f"(c[1]), "+f"(c[2]), "+f"(c[3])
        : "r"(a0), "r"(a1), "r"(a2), "r"(a3), "r"(b0), "r"(b1));
}

// RoPE: tables are TILED (cos[s,j] = cos(t * freqs[j mod 32])) but rotation
// pairs ADJACENT elements (2i, 2i+1) -- exactly as the reference does.
__device__ __forceinline__ void rope_pair(float& e, float& o, int t, int d /*even*/) {
    const float LOG2_10000_OVER_32 = 0.41524101186092028f;
    int   i0  = d & 31;
    float fr0 = exp2f(-(float)i0       * LOG2_10000_OVER_32);
    float fr1 = exp2f(-(float)(i0 + 1) * LOG2_10000_OVER_32);
    float tf  = (float)t;
    float s0, c0, s1, c1;
    sincosf(tf * fr0, &s0, &c0);
    sincosf(tf * fr1, &s1, &c1);
    float ne = e * c0 - o * s0;
    float no = o * c1 + e * s1;
    e = ne; o = no;
}

// ---------------- projection / output GEMM (tf32 mma, 64x64x16 tiles) -------
// MODE: 0 = Q proj (+RoPE, out g_Q [b,h,s,d])
//       1 = K proj (+RoPE, out g_K)
//       2 = V proj (out g_V)
//       5 = output  out = O @ Wo + bo
template <int MODE>
__global__ void __launch_bounds__(128) gemm_k(const float* __restrict__ Ain,
                                              const float* __restrict__ Bin,
                                              float*       __restrict__ Cout,
                                              const float* __restrict__ bias) {
    constexpr int KDIM = 1024;
    constexpr int LDA  = 1024;
    constexpr int LDB  = 1024;

    const int tid  = threadIdx.x;
    const int lane = tid & 31;
    const int warp = tid >> 5;
    const int wm   = warp >> 1;
    const int wn   = warp & 1;
    const int mBase = blockIdx.y * 64;
    const int nBase = blockIdx.x * 64;

    const float* A  = (MODE == 5) ? g_O : Ain;
    const float* Bp = Bin;

    __shared__ float As[64 * 20];
    __shared__ float Bs[16 * 72];

    float acc[2][4][4];
    #pragma unroll
    for (int i = 0; i < 2; i++)
        #pragma unroll
        for (int j = 0; j < 4; j++)
            #pragma unroll
            for (int k = 0; k < 4; k++) acc[i][j][k] = 0.f;

    for (int k0 = 0; k0 < KDIM; k0 += 16) {
        #pragma unroll
        for (int i = 0; i < 2; i++) {
            int idx = tid + i * 128;
            int r = idx >> 2, c4 = (idx & 3) * 4;
            float4 v = *reinterpret_cast<const float4*>(A + (size_t)(mBase + r) * LDA + k0 + c4);
            float* d = &As[r * 20 + c4];
            d[0] = to_tf32(v.x); d[1] = to_tf32(v.y); d[2] = to_tf32(v.z); d[3] = to_tf32(v.w);
        }
        #pragma unroll
        for (int i = 0; i < 2; i++) {
            int idx = tid + i * 128;
            int r = idx >> 4, c4 = (idx & 15) * 4;
            float4 v = *reinterpret_cast<const float4*>(Bp + (size_t)(k0 + r) * LDB + nBase + c4);
            float* d = &Bs[r * 72 + c4];
            d[0] = to_tf32(v.x); d[1] = to_tf32(v.y); d[2] = to_tf32(v.z); d[3] = to_tf32(v.w);
        }
        __syncthreads();

        #pragma unroll
        for (int kk = 0; kk < 16; kk += 8) {
            const int cc = kk + (lane & 3);
            uint32_t af[2][4];
            #pragma unroll
            for (int mt = 0; mt < 2; mt++) {
                int r0 = (wm * 32 + mt * 16 + (lane >> 2)) * 20;
                af[mt][0] = __float_as_uint(As[r0 + cc]);
                af[mt][1] = __float_as_uint(As[r0 + 160 + cc]);
                af[mt][2] = __float_as_uint(As[r0 + cc + 4]);
                af[mt][3] = __float_as_uint(As[r0 + 160 + cc + 4]);
            }
            uint32_t bf[4][2];
            #pragma unroll
            for (int nt = 0; nt < 4; nt++) {
                int nb = wn * 32 + nt * 8 + (lane >> 2);
                bf[nt][0] = __float_as_uint(Bs[(kk + (lane & 3)) * 72 + nb]);
                bf[nt][1] = __float_as_uint(Bs[(kk + (lane & 3) + 4) * 72 + nb]);
            }
            #pragma unroll
            for (int mt = 0; mt < 2; mt++)
                #pragma unroll
                for (int nt = 0; nt < 4; nt++)
                    mma8(acc[mt][nt], af[mt][0], af[mt][1], af[mt][2], af[mt][3],
                         bf[nt][0], bf[nt][1]);
        }
        __syncthreads();
    }

    // --- epilogue ---
    #pragma unroll
    for (int mt = 0; mt < 2; mt++) {
        #pragma unroll
        for (int nt = 0; nt < 4; nt++) {
            int row = mBase + wm * 32 + mt * 16 + (lane >> 2);
            int col = nBase + wn * 32 + nt * 8 + 2 * (lane & 3);
            #pragma unroll
            for (int half = 0; half < 2; half++) {
                int   rr = row + half * 8;
                float e  = acc[mt][nt][half * 2 + 0];
                float o  = acc[mt][nt][half * 2 + 1];
                if constexpr (MODE <= 1) rope_pair(e, o, rr & (SEQ - 1), col & (HDIM - 1));
                if constexpr (MODE <= 2) {
                    int b = rr >> 9, s = rr & (SEQ - 1);
                    int h = col >> 6, d = col & (HDIM - 1);
                    float* out = (MODE == 0) ? g_Q : ((MODE == 1) ? g_K : g_V);
                    size_t off = (((size_t)(b * HEADS + h)) * SEQ + s) * HDIM + d;
                    *reinterpret_cast<float2*>(out + off) = make_float2(e, o);
                } else {
                    size_t off = (size_t)rr * DIMM + col;
                    *reinterpret_cast<float2*>(Cout + off) =
                        make_float2(e + bias[col], o + bias[col + 1]);
                }
            }
        }
    }
}

// ---------------- fused flash attention (scores + softmax + PV) -------------
// One CTA per (z = b*H+h, 64-row q tile). 4 warps, each owns 16 q rows.
// Q held in registers as mma A-fragments; K/V tiles streamed via smem;
// P re-enters the tensor pipe through the (dead) K smem buffer.
__global__ void __launch_bounds__(128) flash_k() {
    const int z     = blockIdx.y;
    const int qBase = blockIdx.x * 64;
    const int lane  = threadIdx.x & 31;
    const int warp  = threadIdx.x >> 5;

    const float* Qp = g_Q + (size_t)z * SEQ * HDIM;
    const float* Kp = g_K + (size_t)z * SEQ * HDIM;
    const float* Vp = g_V + (size_t)z * SEQ * HDIM;

    __shared__ float KPs[64 * 68];   // K tile, reused as P tile after QK^T
    __shared__ float Vs [64 * 68];

    // Q A-fragments (m16n8k8 row.col): rows r0, r0+8; k covers d=0..63
    uint32_t qa[8][4];
    {
        const int r0 = qBase + warp * 16 + (lane >> 2);
        #pragma unroll
        for (int kk = 0; kk < 8; kk++) {
            int c = kk * 8 + (lane & 3);
            qa[kk][0] = __float_as_uint(to_tf32(Qp[(size_t)r0       * HDIM + c]));
            qa[kk][1] = __float_as_uint(to_tf32(Qp[(size_t)(r0 + 8) * HDIM + c]));
            qa[kk][2] = __float_as_uint(to_tf32(Qp[(size_t)r0       * HDIM + c + 4]));
            qa[kk][3] = __float_as_uint(to_tf32(Qp[(size_t)(r0 + 8) * HDIM + c + 4]));
        }
    }

    float m0 = -1e30f, m1 = -1e30f, l0 = 0.f, l1 = 0.f;
    float o[8][4];
    #pragma unroll
    for (int nt = 0; nt < 8; nt++)
        #pragma unroll
        for (int i = 0; i < 4; i++) o[nt][i] = 0.f;

    for (int kt = 0; kt < 8; kt++) {
        __syncthreads();   // protect KPs/Vs from previous iteration's readers
        const float* Kt = Kp + (size_t)kt * 64 * HDIM;
        const float* Vt = Vp + (size_t)kt * 64 * HDIM;
        // 64x64 tile = 4096 floats = 1024 float4 -> 8 iterations of 128 threads
        #pragma unroll
        for (int i = 0; i < 8; i++) {
            int idx = threadIdx.x + i * 128;
            int rr = idx >> 4, cc = (idx & 15) * 4;
            float4 kq = *reinterpret_cast<const float4*>(Kt + rr * HDIM + cc);
            float4 vq = *reinterpret_cast<const float4*>(Vt + rr * HDIM + cc);
            float* kd = &KPs[rr * 68 + cc];
            kd[0] = to_tf32(kq.x); kd[1] = to_tf32(kq.y); kd[2] = to_tf32(kq.z); kd[3] = to_tf32(kq.w);
            float* vd = &Vs[rr * 68 + cc];
            vd[0] = to_tf32(vq.x); vd[1] = to_tf32(vq.y); vd[2] = to_tf32(vq.z); vd[3] = to_tf32(vq.w);
        }
        __syncthreads();

        // ---- S = Q K^T (16x64 per warp) ----
        float s[8][4];
        #pragma unroll
        for (int nt = 0; nt < 8; nt++)
            #pragma unroll
            for (int i = 0; i < 4; i++) s[nt][i] = 0.f;
        #pragma unroll
        for (int kk = 0; kk < 8; kk++) {
            const int d0 = kk * 8 + (lane & 3);
            #pragma unroll
            for (int nt = 0; nt < 8; nt++) {
                const int kvr = nt * 8 + (lane >> 2);
                uint32_t b0 = __float_as_uint(KPs[kvr * 68 + d0]);
                uint32_t b1 = __float_as_uint(KPs[kvr * 68 + d0 + 4]);
                mma8(s[nt], qa[kk][0], qa[kk][1], qa[kk][2], qa[kk][3], b0, b1);
            }
        }

        // ---- online softmax ----
        float mr0 = -1e30f, mr1 = -1e30f;
        #pragma unroll
        for (int nt = 0; nt < 8; nt++) {
            s[nt][0] *= 0.125f; s[nt][1] *= 0.125f;
            s[nt][2] *= 0.125f; s[nt][3] *= 0.125f;
            mr0 = fmaxf(mr0, fmaxf(s[nt][0], s[nt][1]));
            mr1 = fmaxf(mr1, fmaxf(s[nt][2], s[nt][3]));
        }
        mr0 = fmaxf(mr0, __shfl_xor_sync(0xffffffffu, mr0, 1));
        mr0 = fmaxf(mr0, __shfl_xor_sync(0xffffffffu, mr0, 2));
        mr1 = fmaxf(mr1, __shfl_xor_sync(0xffffffffu, mr1, 1));
        mr1 = fmaxf(mr1, __shfl_xor_sync(0xffffffffu, mr1, 2));

        float nm0 = fmaxf(m0, mr0), nm1 = fmaxf(m1, mr1);
        float f0 = __expf(m0 - nm0), f1 = __expf(m1 - nm1);
        m0 = nm0; m1 = nm1;

        float sum0 = 0.f, sum1 = 0.f;
        #pragma unroll
        for (int nt = 0; nt < 8; nt++) {
            s[nt][0] = __expf(s[nt][0] - m0);
            s[nt][1] = __expf(s[nt][1] - m0);
            s[nt][2] = __expf(s[nt][2] - m1);
            s[nt][3] = __expf(s[nt][3] - m1);
            sum0 += s[nt][0] + s[nt][1];
            sum1 += s[nt][2] + s[nt][3];
        }
        sum0 += __shfl_xor_sync(0xffffffffu, sum0, 1);
        sum0 += __shfl_xor_sync(0xffffffffu, sum0, 2);
        sum1 += __shfl_xor_sync(0xffffffffu, sum1, 1);
        sum1 += __shfl_xor_sync(0xffffffffu, sum1, 2);
        l0 = l0 * f0 + sum0;
        l1 = l1 * f1 + sum1;

        #pragma unroll
        for (int nt = 0; nt < 8; nt++) {
            o[nt][0] *= f0; o[nt][1] *= f0;
            o[nt][2] *= f1; o[nt][3] *= f1;
        }

        // ---- P -> smem (reuse K buffer), then O += P V ----
        __syncthreads();   // all warps done reading K from KPs
        {
            const int pr = warp * 16 + (lane >> 2);
            #pragma unroll
            for (int nt = 0; nt < 8; nt++) {
                int c = nt * 8 + 2 * (lane & 3);
                KPs[pr * 68 + c]           = to_tf32(s[nt][0]);
                KPs[pr * 68 + c + 1]       = to_tf32(s[nt][1]);
                KPs[(pr + 8) * 68 + c]     = to_tf32(s[nt][2]);
                KPs[(pr + 8) * 68 + c + 1] = to_tf32(s[nt][3]);
            }
        }
        __syncwarp();      // P rows are warp-private; warp-level visibility suffices

        #pragma unroll
        for (int kk = 0; kk < 8; kk++) {
            const int pq = warp * 16 + (lane >> 2);
            const int kv = kk * 8 + (lane & 3);
            uint32_t pa0 = __float_as_uint(KPs[pq * 68 + kv]);
            uint32_t pa1 = __float_as_uint(KPs[(pq + 8) * 68 + kv]);
            uint32_t pa2 = __float_as_uint(KPs[pq * 68 + kv + 4]);
            uint32_t pa3 = __float_as_uint(KPs[(pq + 8) * 68 + kv + 4]);
            #pragma unroll
            for (int nt = 0; nt < 8; nt++) {
                const int dc = nt * 8 + (lane >> 2);
                uint32_t b0 = __float_as_uint(Vs[kv * 68 + dc]);
                uint32_t b1 = __float_as_uint(Vs[(kv + 4) * 68 + dc]);
                mma8(o[nt], pa0, pa1, pa2, pa3, b0, b1);
            }
        }
    }

    // ---- epilogue: O /= l, write [b, s, h*64+d] ----
    const float inv0 = 1.f / l0, inv1 = 1.f / l1;
    const int b = z >> 4, h = z & 15;
    const int row = qBase + warp * 16 + (lane >> 2);
    #pragma unroll
    for (int nt = 0; nt < 8; nt++) {
        int col = h * HDIM + nt * 8 + 2 * (lane & 3);
        *reinterpret_cast<float2*>(g_O + (size_t)(b * SEQ + row) * DIMM + col)
            = make_float2(o[nt][0] * inv0, o[nt][1] * inv0);
        *reinterpret_cast<float2*>(g_O + (size_t)(b * SEQ + row + 8) * DIMM + col)
            = make_float2(o[nt][2] * inv1, o[nt][3] * inv1);
    }
}

// ---------------- launch -----------------------------------------------------
extern "C" void kernel_launch(void* const* d_in, const int* in_sizes, int n_in,
                              void* d_out, int out_size) {
    (void)in_sizes; (void)n_in; (void)out_size;
    const float* x   = (const float*)d_in[0];
    const float* ctx = (const float*)d_in[1];
    const float* Wq  = (const float*)d_in[2];
    const float* Wk  = (const float*)d_in[3];
    const float* Wv  = (const float*)d_in[4];
    const float* Wo  = (const float*)d_in[5];
    const float* bo  = (const float*)d_in[6];
    float* out = (float*)d_out;

    dim3 blk(128);
    gemm_k<0><<<dim3(16, 128, 1), blk>>>(x,   Wq, nullptr, nullptr);
    gemm_k<1><<<dim3(16, 128, 1), blk>>>(ctx, Wk, nullptr, nullptr);
    gemm_k<2><<<dim3(16, 128, 1), blk>>>(ctx, Wv, nullptr, nullptr);
    flash_k<<<dim3(8, 256, 1), blk>>>();
    gemm_k<5><<<dim3(16, 128, 1), blk>>>(nullptr, Wo, out, bo);
}

// round 4
// speedup vs baseline: 1.3997x; 1.2284x over previous
#include <cuda_runtime.h>
#include <cstdint>

// Problem constants
#define DIMM  1024
#define HEADS 16
#define HDIM  64
#define BATCH 16
#define SEQ   512

// ---------------- scratch (device globals; no cudaMalloc allowed) ----------
__device__ float g_Q[(size_t)BATCH*HEADS*SEQ*HDIM];   // [b,h,s,d]  32 MB
__device__ float g_K[(size_t)BATCH*HEADS*SEQ*HDIM];   // 32 MB
__device__ float g_V[(size_t)BATCH*HEADS*SEQ*HDIM];   // 32 MB
__device__ float g_O[(size_t)BATCH*SEQ*DIMM];         // [b,s,h*d]  32 MB

// ---------------- helpers ---------------------------------------------------
__device__ __forceinline__ float to_tf32(float x) {
    uint32_t u;
    asm("cvt.rna.tf32.f32 %0, %1;" : "=r"(u) : "f"(x));
    return __uint_as_float(u);
}
__device__ __forceinline__ uint32_t to_tf32u(float x) {
    uint32_t u;
    asm("cvt.rna.tf32.f32 %0, %1;" : "=r"(u) : "f"(x));
    return u;
}

__device__ __forceinline__ void mma8(float* c,
                                     uint32_t a0, uint32_t a1, uint32_t a2, uint32_t a3,
                                     uint32_t b0, uint32_t b1) {
    asm volatile(
        "mma.sync.aligned.m16n8k8.row.col.f32.tf32.tf32.f32 "
        "{%0,%1,%2,%3},{%4,%5,%6,%7},{%8,%9},{%0,%1,%2,%3};"
        : "+f"(c[0]), "+f"(c[1]), "+f"(c[2]), "+f"(c[3])
        : "r"(a0), "r"(a1), "r"(a2), "r"(a3), "r"(b0), "r"(b1));
}

__device__ __forceinline__ void cp_async16(uint32_t s, const void* g) {
    asm volatile("cp.async.cg.shared.global [%0], [%1], 16;" :: "r"(s), "l"(g));
}

// RoPE: tables are TILED (cos[s,j] = cos(t * freqs[j mod 32])) but rotation
// pairs ADJACENT elements (2i, 2i+1) -- exactly as the reference does.
__device__ __forceinline__ void rope_pair(float& e, float& o, int t, int d /*even*/) {
    const float LOG2_10000_OVER_32 = 0.41524101186092028f;
    int   i0  = d & 31;
    float fr0 = exp2f(-(float)i0       * LOG2_10000_OVER_32);
    float fr1 = exp2f(-(float)(i0 + 1) * LOG2_10000_OVER_32);
    float tf  = (float)t;
    float s0, c0, s1, c1;
    sincosf(tf * fr0, &s0, &c0);
    sincosf(tf * fr1, &s1, &c1);
    float ne = e * c0 - o * s0;
    float no = o * c1 + e * s1;
    e = ne; o = no;
}

// ---------------- pipelined projection / output GEMM ------------------------
// 128x128 tile, BK=16, 256 threads (2x4 warps, 64x32 per warp),
// cp.async double-buffered smem, tf32 mma.
// MODE: 0 = Q proj (+RoPE, out g_Q [b,h,s,d])
//       1 = K proj (+RoPE, out g_K)
//       2 = V proj (out g_V)
//       5 = output  out = O @ Wo + bo
template <int MODE>
__global__ void __launch_bounds__(256) gemm2_k(const float* __restrict__ Ain,
                                               const float* __restrict__ Bin,
                                               float*       __restrict__ Cout,
                                               const float* __restrict__ bias) {
    const int tid  = threadIdx.x;
    const int lane = tid & 31;
    const int warp = tid >> 5;
    const int wm   = warp >> 2;         // 0..1  (64 rows each)
    const int wn   = warp & 3;          // 0..3  (32 cols each)
    const int mBase = blockIdx.y * 128;
    const int nBase = blockIdx.x * 128;

    const float* A = (MODE == 5) ? g_O : Ain;
    const float* B = Bin;

    __shared__ float As[2][128 * 20];   // stride 20 (bank-conflict free)
    __shared__ float Bs[2][16 * 136];   // stride 136 == 8 mod 32

    // cp.async tile loaders (raw fp32; tf32 conversion at fragment read)
    auto load_tiles = [&](int k0, int buf) {
        #pragma unroll
        for (int i = 0; i < 2; i++) {
            int idx = tid + i * 256;
            int r = idx >> 2, c4 = (idx & 3) * 4;
            uint32_t s = (uint32_t)__cvta_generic_to_shared(&As[buf][r * 20 + c4]);
            cp_async16(s, A + (size_t)(mBase + r) * 1024 + k0 + c4);
        }
        #pragma unroll
        for (int i = 0; i < 2; i++) {
            int idx = tid + i * 256;
            int r = idx >> 5, c4 = (idx & 31) * 4;
            uint32_t s = (uint32_t)__cvta_generic_to_shared(&Bs[buf][r * 136 + c4]);
            cp_async16(s, B + (size_t)(k0 + r) * 1024 + nBase + c4);
        }
        asm volatile("cp.async.commit_group;");
    };

    float acc[4][4][4];
    #pragma unroll
    for (int i = 0; i < 4; i++)
        #pragma unroll
        for (int j = 0; j < 4; j++)
            #pragma unroll
            for (int k = 0; k < 4; k++) acc[i][j][k] = 0.f;

    load_tiles(0, 0);
    asm volatile("cp.async.wait_group 0;");
    __syncthreads();

    for (int k0 = 0; k0 < 1024; k0 += 16) {
        const int buf = (k0 >> 4) & 1;
        if (k0 + 16 < 1024) load_tiles(k0 + 16, buf ^ 1);

        const float* Ab = As[buf];
        const float* Bb = Bs[buf];
        #pragma unroll
        for (int kk = 0; kk < 16; kk += 8) {
            const int cc = kk + (lane & 3);
            uint32_t af[4][4];
            #pragma unroll
            for (int mt = 0; mt < 4; mt++) {
                int r0 = (wm * 64 + mt * 16 + (lane >> 2)) * 20;
                af[mt][0] = to_tf32u(Ab[r0 + cc]);
                af[mt][1] = to_tf32u(Ab[r0 + 160 + cc]);       // +8 rows
                af[mt][2] = to_tf32u(Ab[r0 + cc + 4]);
                af[mt][3] = to_tf32u(Ab[r0 + 160 + cc + 4]);
            }
            uint32_t bf[4][2];
            #pragma unroll
            for (int nt = 0; nt < 4; nt++) {
                int nb = wn * 32 + nt * 8 + (lane >> 2);
                bf[nt][0] = to_tf32u(Bb[cc * 136 + nb]);
                bf[nt][1] = to_tf32u(Bb[(cc + 4) * 136 + nb]);
            }
            #pragma unroll
            for (int mt = 0; mt < 4; mt++)
                #pragma unroll
                for (int nt = 0; nt < 4; nt++)
                    mma8(acc[mt][nt], af[mt][0], af[mt][1], af[mt][2], af[mt][3],
                         bf[nt][0], bf[nt][1]);
        }
        asm volatile("cp.async.wait_group 0;");
        __syncthreads();
    }

    // --- epilogue ---
    #pragma unroll
    for (int mt = 0; mt < 4; mt++) {
        #pragma unroll
        for (int nt = 0; nt < 4; nt++) {
            int row = mBase + wm * 64 + mt * 16 + (lane >> 2);
            int col = nBase + wn * 32 + nt * 8 + 2 * (lane & 3);
            #pragma unroll
            for (int half = 0; half < 2; half++) {
                int   rr = row + half * 8;
                float e  = acc[mt][nt][half * 2 + 0];
                float o  = acc[mt][nt][half * 2 + 1];
                if constexpr (MODE <= 1) rope_pair(e, o, rr & (SEQ - 1), col & (HDIM - 1));
                if constexpr (MODE <= 2) {
                    int b = rr >> 9, s = rr & (SEQ - 1);
                    int h = col >> 6, d = col & (HDIM - 1);
                    float* out = (MODE == 0) ? g_Q : ((MODE == 1) ? g_K : g_V);
                    size_t off = (((size_t)(b * HEADS + h)) * SEQ + s) * HDIM + d;
                    *reinterpret_cast<float2*>(out + off) = make_float2(e, o);
                } else {
                    size_t off = (size_t)rr * DIMM + col;
                    *reinterpret_cast<float2*>(Cout + off) =
                        make_float2(e + bias[col], o + bias[col + 1]);
                }
            }
        }
    }
}

// ---------------- fused flash attention (scores + softmax + PV) -------------
// One CTA per (z = b*H+h, 64-row q tile). 4 warps, each owns 16 q rows.
__global__ void __launch_bounds__(128) flash_k() {
    const int z     = blockIdx.y;
    const int qBase = blockIdx.x * 64;
    const int lane  = threadIdx.x & 31;
    const int warp  = threadIdx.x >> 5;

    const float* Qp = g_Q + (size_t)z * SEQ * HDIM;
    const float* Kp = g_K + (size_t)z * SEQ * HDIM;
    const float* Vp = g_V + (size_t)z * SEQ * HDIM;

    __shared__ float KPs[64 * 68];   // K tile, reused as P tile after QK^T
    __shared__ float Vs [64 * 68];

    uint32_t qa[8][4];
    {
        const int r0 = qBase + warp * 16 + (lane >> 2);
        #pragma unroll
        for (int kk = 0; kk < 8; kk++) {
            int c = kk * 8 + (lane & 3);
            qa[kk][0] = __float_as_uint(to_tf32(Qp[(size_t)r0       * HDIM + c]));
            qa[kk][1] = __float_as_uint(to_tf32(Qp[(size_t)(r0 + 8) * HDIM + c]));
            qa[kk][2] = __float_as_uint(to_tf32(Qp[(size_t)r0       * HDIM + c + 4]));
            qa[kk][3] = __float_as_uint(to_tf32(Qp[(size_t)(r0 + 8) * HDIM + c + 4]));
        }
    }

    float m0 = -1e30f, m1 = -1e30f, l0 = 0.f, l1 = 0.f;
    float o[8][4];
    #pragma unroll
    for (int nt = 0; nt < 8; nt++)
        #pragma unroll
        for (int i = 0; i < 4; i++) o[nt][i] = 0.f;

    for (int kt = 0; kt < 8; kt++) {
        __syncthreads();
        const float* Kt = Kp + (size_t)kt * 64 * HDIM;
        const float* Vt = Vp + (size_t)kt * 64 * HDIM;
        #pragma unroll
        for (int i = 0; i < 8; i++) {
            int idx = threadIdx.x + i * 128;
            int rr = idx >> 4, cc = (idx & 15) * 4;
            float4 kq = *reinterpret_cast<const float4*>(Kt + rr * HDIM + cc);
            float4 vq = *reinterpret_cast<const float4*>(Vt + rr * HDIM + cc);
            float* kd = &KPs[rr * 68 + cc];
            kd[0] = to_tf32(kq.x); kd[1] = to_tf32(kq.y); kd[2] = to_tf32(kq.z); kd[3] = to_tf32(kq.w);
            float* vd = &Vs[rr * 68 + cc];
            vd[0] = to_tf32(vq.x); vd[1] = to_tf32(vq.y); vd[2] = to_tf32(vq.z); vd[3] = to_tf32(vq.w);
        }
        __syncthreads();

        float s[8][4];
        #pragma unroll
        for (int nt = 0; nt < 8; nt++)
            #pragma unroll
            for (int i = 0; i < 4; i++) s[nt][i] = 0.f;
        #pragma unroll
        for (int kk = 0; kk < 8; kk++) {
            const int d0 = kk * 8 + (lane & 3);
            #pragma unroll
            for (int nt = 0; nt < 8; nt++) {
                const int kvr = nt * 8 + (lane >> 2);
                uint32_t b0 = __float_as_uint(KPs[kvr * 68 + d0]);
                uint32_t b1 = __float_as_uint(KPs[kvr * 68 + d0 + 4]);
                mma8(s[nt], qa[kk][0], qa[kk][1], qa[kk][2], qa[kk][3], b0, b1);
            }
        }

        float mr0 = -1e30f, mr1 = -1e30f;
        #pragma unroll
        for (int nt = 0; nt < 8; nt++) {
            s[nt][0] *= 0.125f; s[nt][1] *= 0.125f;
            s[nt][2] *= 0.125f; s[nt][3] *= 0.125f;
            mr0 = fmaxf(mr0, fmaxf(s[nt][0], s[nt][1]));
            mr1 = fmaxf(mr1, fmaxf(s[nt][2], s[nt][3]));
        }
        mr0 = fmaxf(mr0, __shfl_xor_sync(0xffffffffu, mr0, 1));
        mr0 = fmaxf(mr0, __shfl_xor_sync(0xffffffffu, mr0, 2));
        mr1 = fmaxf(mr1, __shfl_xor_sync(0xffffffffu, mr1, 1));
        mr1 = fmaxf(mr1, __shfl_xor_sync(0xffffffffu, mr1, 2));

        float nm0 = fmaxf(m0, mr0), nm1 = fmaxf(m1, mr1);
        float f0 = __expf(m0 - nm0), f1 = __expf(m1 - nm1);
        m0 = nm0; m1 = nm1;

        float sum0 = 0.f, sum1 = 0.f;
        #pragma unroll
        for (int nt = 0; nt < 8; nt++) {
            s[nt][0] = __expf(s[nt][0] - m0);
            s[nt][1] = __expf(s[nt][1] - m0);
            s[nt][2] = __expf(s[nt][2] - m1);
            s[nt][3] = __expf(s[nt][3] - m1);
            sum0 += s[nt][0] + s[nt][1];
            sum1 += s[nt][2] + s[nt][3];
        }
        sum0 += __shfl_xor_sync(0xffffffffu, sum0, 1);
        sum0 += __shfl_xor_sync(0xffffffffu, sum0, 2);
        sum1 += __shfl_xor_sync(0xffffffffu, sum1, 1);
        sum1 += __shfl_xor_sync(0xffffffffu, sum1, 2);
        l0 = l0 * f0 + sum0;
        l1 = l1 * f1 + sum1;

        #pragma unroll
        for (int nt = 0; nt < 8; nt++) {
            o[nt][0] *= f0; o[nt][1] *= f0;
            o[nt][2] *= f1; o[nt][3] *= f1;
        }

        __syncthreads();
        {
            const int pr = warp * 16 + (lane >> 2);
            #pragma unroll
            for (int nt = 0; nt < 8; nt++) {
                int c = nt * 8 + 2 * (lane & 3);
                KPs[pr * 68 + c]           = to_tf32(s[nt][0]);
                KPs[pr * 68 + c + 1]       = to_tf32(s[nt][1]);
                KPs[(pr + 8) * 68 + c]     = to_tf32(s[nt][2]);
                KPs[(pr + 8) * 68 + c + 1] = to_tf32(s[nt][3]);
            }
        }
        __syncwarp();

        #pragma unroll
        for (int kk = 0; kk < 8; kk++) {
            const int pq = warp * 16 + (lane >> 2);
            const int kv = kk * 8 + (lane & 3);
            uint32_t pa0 = __float_as_uint(KPs[pq * 68 + kv]);
            uint32_t pa1 = __float_as_uint(KPs[(pq + 8) * 68 + kv]);
            uint32_t pa2 = __float_as_uint(KPs[pq * 68 + kv + 4]);
            uint32_t pa3 = __float_as_uint(KPs[(pq + 8) * 68 + kv + 4]);
            #pragma unroll
            for (int nt = 0; nt < 8; nt++) {
                const int dc = nt * 8 + (lane >> 2);
                uint32_t b0 = __float_as_uint(Vs[kv * 68 + dc]);
                uint32_t b1 = __float_as_uint(Vs[(kv + 4) * 68 + dc]);
                mma8(o[nt], pa0, pa1, pa2, pa3, b0, b1);
            }
        }
    }

    const float inv0 = 1.f / l0, inv1 = 1.f / l1;
    const int b = z >> 4, h = z & 15;
    const int row = qBase + warp * 16 + (lane >> 2);
    #pragma unroll
    for (int nt = 0; nt < 8; nt++) {
        int col = h * HDIM + nt * 8 + 2 * (lane & 3);
        *reinterpret_cast<float2*>(g_O + (size_t)(b * SEQ + row) * DIMM + col)
            = make_float2(o[nt][0] * inv0, o[nt][1] * inv0);
        *reinterpret_cast<float2*>(g_O + (size_t)(b * SEQ + row + 8) * DIMM + col)
            = make_float2(o[nt][2] * inv1, o[nt][3] * inv1);
    }
}

// ---------------- launch -----------------------------------------------------
extern "C" void kernel_launch(void* const* d_in, const int* in_sizes, int n_in,
                              void* d_out, int out_size) {
    (void)in_sizes; (void)n_in; (void)out_size;
    const float* x   = (const float*)d_in[0];
    const float* ctx = (const float*)d_in[1];
    const float* Wq  = (const float*)d_in[2];
    const float* Wk  = (const float*)d_in[3];
    const float* Wv  = (const float*)d_in[4];
    const float* Wo  = (const float*)d_in[5];
    const float* bo  = (const float*)d_in[6];
    float* out = (float*)d_out;

    dim3 g(8, 64), b2(256);
    gemm2_k<0><<<g, b2>>>(x,   Wq, nullptr, nullptr);
    gemm2_k<1><<<g, b2>>>(ctx, Wk, nullptr, nullptr);
    gemm2_k<2><<<g, b2>>>(ctx, Wv, nullptr, nullptr);
    flash_k<<<dim3(8, 256, 1), dim3(128)>>>();
    gemm2_k<5><<<g, b2>>>(nullptr, Wo, out, bo);
}